// round 1
// baseline (speedup 1.0000x reference)
#include <cuda_runtime.h>
#include <math.h>

#define NN 100000
#define EE 1600000
#define DD 64
#define NEG 0.01f

// ---------------- scratch (device globals; no allocation allowed) ----------
__device__ float g_h[NN * DD];     // GEMM output (x @ W) for current layer
__device__ float g_bufA[NN * DD];  // ping
__device__ float g_bufB[NN * DD];  // pong
__device__ int   g_cnt[NN];        // in-degree histogram (excl. self loop)
__device__ int   g_rowptr[NN];     // CSR row starts
__device__ int   g_pos[NN];        // running scatter cursor
__device__ int   g_col[EE];        // CSR column (src) indices
__device__ float g_dinv[NN];       // deg^-1/2
__device__ int   g_bsum[128];      // scan block sums (98 used)

// ---------------- CSR build ------------------------------------------------
__global__ void k_zero_cnt() {
    int i = blockIdx.x * blockDim.x + threadIdx.x;
    if (i < NN) g_cnt[i] = 0;
}

__global__ void k_hist(const int* __restrict__ dst) {
    int e = blockIdx.x * blockDim.x + threadIdx.x;
    if (e < EE) atomicAdd(&g_cnt[dst[e]], 1);
}

// block-wide inclusive scan (1024 elems/block), writes exclusive partials
__global__ void k_scanA() {
    __shared__ int s[1024];
    int tid = threadIdx.x;
    int i = blockIdx.x * 1024 + tid;
    int v = (i < NN) ? g_cnt[i] : 0;
    if (i < NN) g_dinv[i] = rsqrtf((float)(v + 1));
    s[tid] = v;
    __syncthreads();
    #pragma unroll
    for (int off = 1; off < 1024; off <<= 1) {
        int t = (tid >= off) ? s[tid - off] : 0;
        __syncthreads();
        s[tid] += t;
        __syncthreads();
    }
    if (i < NN) g_rowptr[i] = s[tid] - v;   // exclusive within block
    if (tid == 1023) g_bsum[blockIdx.x] = s[1023];
}

__global__ void k_scanB(int nb) {
    if (threadIdx.x == 0 && blockIdx.x == 0) {
        int run = 0;
        for (int b = 0; b < nb; b++) { int t = g_bsum[b]; g_bsum[b] = run; run += t; }
    }
}

__global__ void k_scanC() {
    int i = blockIdx.x * blockDim.x + threadIdx.x;
    if (i < NN) {
        int rp = g_rowptr[i] + g_bsum[i >> 10];
        g_rowptr[i] = rp;
        g_pos[i] = rp;
    }
}

__global__ void k_scatter(const int* __restrict__ src, const int* __restrict__ dst) {
    int e = blockIdx.x * blockDim.x + threadIdx.x;
    if (e < EE) {
        int d = dst[e];
        int p = atomicAdd(&g_pos[d], 1);
        g_col[p] = src[e];
    }
}

// ---------------- GEMM: out[N,64] = in[N,64] @ W[64,64] --------------------
// 256 threads / block, 16 rows / block. W and a 16-row x-tile in smem.
__global__ void k_gemm(const float* __restrict__ in, const float* __restrict__ W,
                       float* __restrict__ out) {
    __shared__ float Ws[64 * 64];
    __shared__ float Xs[16 * 64];
    int tid = threadIdx.x;
    #pragma unroll
    for (int j = tid; j < 4096; j += 256) Ws[j] = W[j];
    int rowbase = blockIdx.x * 16;
    // 16 rows * 64 floats = 256 float4, fully coalesced
    ((float4*)Xs)[tid] = ((const float4*)(in + rowbase * 64))[tid];
    __syncthreads();

    int r  = tid >> 4;          // 0..15 local row
    int c4 = (tid & 15) * 4;    // 4 output cols per thread
    float a0 = 0.f, a1 = 0.f, a2 = 0.f, a3 = 0.f;
    const float* xr = Xs + r * 64;
    #pragma unroll
    for (int k = 0; k < 64; k++) {
        float xv = xr[k];
        float4 w = *(const float4*)(Ws + k * 64 + c4);
        a0 += xv * w.x; a1 += xv * w.y; a2 += xv * w.z; a3 += xv * w.w;
    }
    float4 o; o.x = a0; o.y = a1; o.z = a2; o.w = a3;
    *(float4*)(out + (rowbase + r) * 64 + c4) = o;
}

// ---------------- Aggregation + epilogue -----------------------------------
// One warp per dst row. agg = sum_e dinv[src]*h[src]; out = dinv*agg +
// dinv^2*h[i] + b; LeakyReLU. 4-wide software pipeline for MLP.
__global__ void k_agg(const float* __restrict__ h, const float* __restrict__ bias,
                      float* __restrict__ out) {
    int wid  = (blockIdx.x * blockDim.x + threadIdx.x) >> 5;
    int lane = threadIdx.x & 31;
    if (wid >= NN) return;
    int start = g_rowptr[wid];
    int cnt   = g_cnt[wid];
    float di  = g_dinv[wid];
    const float2* h2 = (const float2*)h;

    float a0 = 0.f, a1 = 0.f;
    int j = 0;
    for (; j + 4 <= cnt; j += 4) {
        int s0 = g_col[start + j];
        int s1 = g_col[start + j + 1];
        int s2 = g_col[start + j + 2];
        int s3 = g_col[start + j + 3];
        float c0 = g_dinv[s0], c1 = g_dinv[s1], c2 = g_dinv[s2], c3 = g_dinv[s3];
        float2 v0 = h2[s0 * 32 + lane];
        float2 v1 = h2[s1 * 32 + lane];
        float2 v2 = h2[s2 * 32 + lane];
        float2 v3 = h2[s3 * 32 + lane];
        a0 += c0 * v0.x; a1 += c0 * v0.y;
        a0 += c1 * v1.x; a1 += c1 * v1.y;
        a0 += c2 * v2.x; a1 += c2 * v2.y;
        a0 += c3 * v3.x; a1 += c3 * v3.y;
    }
    for (; j < cnt; j++) {
        int s = g_col[start + j];
        float c = g_dinv[s];
        float2 v = h2[s * 32 + lane];
        a0 += c * v.x; a1 += c * v.y;
    }

    float2 hs = h2[wid * 32 + lane];
    float2 bb = ((const float2*)bias)[lane];
    float d2 = di * di;
    float o0 = di * a0 + d2 * hs.x + bb.x;
    float o1 = di * a1 + d2 * hs.y + bb.y;
    o0 = (o0 >= 0.f) ? o0 : NEG * o0;
    o1 = (o1 >= 0.f) ? o1 : NEG * o1;
    float2 oo; oo.x = o0; oo.y = o1;
    ((float2*)out)[wid * 32 + lane] = oo;
}

// ---------------- launch ----------------------------------------------------
extern "C" void kernel_launch(void* const* d_in, const int* in_sizes, int n_in,
                              void* d_out, int out_size) {
    (void)in_sizes; (void)n_in; (void)out_size;
    const float* x  = (const float*)d_in[0];
    const int*   ei = (const int*)d_in[1];
    const int* src = ei;
    const int* dst = ei + EE;
    const float* Wt[4] = { (const float*)d_in[2], (const float*)d_in[4],
                           (const float*)d_in[6], (const float*)d_in[8] };
    const float* bt[4] = { (const float*)d_in[3], (const float*)d_in[5],
                           (const float*)d_in[7], (const float*)d_in[9] };

    float *p_h, *p_a, *p_b;
    cudaGetSymbolAddress((void**)&p_h, g_h);
    cudaGetSymbolAddress((void**)&p_a, g_bufA);
    cudaGetSymbolAddress((void**)&p_b, g_bufB);

    const int NB_SCAN = (NN + 1023) / 1024;   // 98
    const int NB_N256 = (NN + 255) / 256;     // 391
    const int NB_E256 = (EE + 255) / 256;     // 6250

    // CSR build (edge-structure only; shared by all 4 layers)
    k_zero_cnt<<<NB_N256, 256>>>();
    k_hist<<<NB_E256, 256>>>(dst);
    k_scanA<<<NB_SCAN, 1024>>>();
    k_scanB<<<1, 32>>>(NB_SCAN);
    k_scanC<<<NB_N256, 256>>>();
    k_scatter<<<NB_E256, 256>>>(src, dst);

    const int GEMM_BLOCKS = NN / 16;   // 6250 (exact)
    const int AGG_BLOCKS  = NN / 8;    // 12500 warps-per-row (exact, 8 warps/block)

    // layer 1: x -> bufA
    k_gemm<<<GEMM_BLOCKS, 256>>>(x, Wt[0], p_h);
    k_agg<<<AGG_BLOCKS, 256>>>(p_h, bt[0], p_a);
    // layer 2: bufA -> bufB
    k_gemm<<<GEMM_BLOCKS, 256>>>(p_a, Wt[1], p_h);
    k_agg<<<AGG_BLOCKS, 256>>>(p_h, bt[1], p_b);
    // layer 3: bufB -> bufA
    k_gemm<<<GEMM_BLOCKS, 256>>>(p_b, Wt[2], p_h);
    k_agg<<<AGG_BLOCKS, 256>>>(p_h, bt[2], p_a);
    // layer 4: bufA -> d_out
    k_gemm<<<GEMM_BLOCKS, 256>>>(p_a, Wt[3], p_h);
    k_agg<<<AGG_BLOCKS, 256>>>(p_h, bt[3], (float*)d_out);
}

// round 2
// speedup vs baseline: 1.4328x; 1.4328x over previous
#include <cuda_runtime.h>
#include <math.h>

#define NN 100000
#define EE 1600000
#define DD 64
#define NEG 0.01f

// ---------------- scratch (device globals) ---------------------------------
__device__ float g_h[NN * DD];     // h' = dinv[row] * (in @ W)  (gather buffer)
__device__ float g_bufA[NN * DD];  // ping
__device__ float g_bufB[NN * DD];  // pong
__device__ int   g_cnt[NN];        // in-degree histogram (excl. self loop)
__device__ int   g_rowptr[NN];     // CSR row starts
__device__ int   g_pos[NN];        // running scatter cursor
__device__ int   g_col[EE];        // CSR column (src) indices
__device__ float g_dinv[NN];       // deg^-1/2
__device__ int   g_bsum[128];      // scan block sums (98 used)

// ---------------- f32x2 packed-FMA helpers ---------------------------------
__device__ __forceinline__ unsigned long long splat2(float x) {
    unsigned long long r;
    asm("mov.b64 %0, {%1, %1};" : "=l"(r) : "f"(x));
    return r;
}
__device__ __forceinline__ void ffma2(unsigned long long& d,
                                      unsigned long long a,
                                      unsigned long long b) {
    asm("fma.rn.f32x2 %0, %1, %2, %0;" : "+l"(d) : "l"(a), "l"(b));
}
__device__ __forceinline__ void unpack2(unsigned long long v, float& lo, float& hi) {
    asm("mov.b64 {%0, %1}, %2;" : "=f"(lo), "=f"(hi) : "l"(v));
}

// ---------------- CSR build ------------------------------------------------
__global__ void k_zero_cnt() {
    int i = blockIdx.x * blockDim.x + threadIdx.x;
    if (i < NN) g_cnt[i] = 0;
}

__global__ void k_hist(const int* __restrict__ dst) {
    int e = blockIdx.x * blockDim.x + threadIdx.x;
    if (e < EE) atomicAdd(&g_cnt[dst[e]], 1);
}

// block-wide inclusive scan (1024 elems/block), writes exclusive partials
__global__ void k_scanA() {
    __shared__ int s[1024];
    int tid = threadIdx.x;
    int i = blockIdx.x * 1024 + tid;
    int v = (i < NN) ? g_cnt[i] : 0;
    if (i < NN) g_dinv[i] = rsqrtf((float)(v + 1));
    s[tid] = v;
    __syncthreads();
    #pragma unroll
    for (int off = 1; off < 1024; off <<= 1) {
        int t = (tid >= off) ? s[tid - off] : 0;
        __syncthreads();
        s[tid] += t;
        __syncthreads();
    }
    if (i < NN) g_rowptr[i] = s[tid] - v;   // exclusive within block
    if (tid == 1023) g_bsum[blockIdx.x] = s[1023];
}

// parallel scan of the (<=128) block sums: 1 warp, 4 elems/thread
__global__ void k_scanB(int nb) {
    int lane = threadIdx.x;
    int base = lane * 4;
    int v0 = (base + 0 < nb) ? g_bsum[base + 0] : 0;
    int v1 = (base + 1 < nb) ? g_bsum[base + 1] : 0;
    int v2 = (base + 2 < nb) ? g_bsum[base + 2] : 0;
    int v3 = (base + 3 < nb) ? g_bsum[base + 3] : 0;
    int s1 = v0 + v1, s2 = s1 + v2, s3 = s2 + v3;  // local inclusive
    int tot = s3;
    // warp exclusive scan of tot
    int run = tot;
    #pragma unroll
    for (int off = 1; off < 32; off <<= 1) {
        int t = __shfl_up_sync(0xffffffffu, run, off);
        if (lane >= off) run += t;
    }
    int excl = run - tot;
    if (base + 0 < nb) g_bsum[base + 0] = excl;
    if (base + 1 < nb) g_bsum[base + 1] = excl + v0;
    if (base + 2 < nb) g_bsum[base + 2] = excl + s1;
    if (base + 3 < nb) g_bsum[base + 3] = excl + s2;
}

__global__ void k_scanC() {
    int i = blockIdx.x * blockDim.x + threadIdx.x;
    if (i < NN) {
        int rp = g_rowptr[i] + g_bsum[i >> 10];
        g_rowptr[i] = rp;
        g_pos[i] = rp;
    }
}

__global__ void k_scatter(const int* __restrict__ src, const int* __restrict__ dst) {
    int e = blockIdx.x * blockDim.x + threadIdx.x;
    if (e < EE) {
        int d = dst[e];
        int p = atomicAdd(&g_pos[d], 1);
        g_col[p] = src[e];
    }
}

// ---------------- GEMM: out[N,64] = dinv[row] * (in[N,64] @ W[64,64]) ------
// 256 threads / block, 32 rows / block; each thread: 2 rows x 4 cols,
// accumulated in packed f32x2 (FFMA2).
__global__ void k_gemm(const float* __restrict__ in, const float* __restrict__ W,
                       float* __restrict__ out) {
    __shared__ float Ws[64 * 64];
    __shared__ float Xs[32 * 64];
    int tid = threadIdx.x;
    #pragma unroll
    for (int j = tid; j < 4096; j += 256) Ws[j] = W[j];
    int rowbase = blockIdx.x * 32;
    // 32 rows * 64 floats = 512 float4 -> 2 per thread, coalesced
    ((float4*)Xs)[tid]       = ((const float4*)(in + rowbase * 64))[tid];
    ((float4*)Xs)[tid + 256] = ((const float4*)(in + rowbase * 64))[tid + 256];
    __syncthreads();

    int rp = tid >> 4;            // 0..15 row pair
    int r0 = rp * 2;
    int c4 = (tid & 15) * 4;      // 4 output cols
    unsigned long long a00 = 0, a01 = 0, a10 = 0, a11 = 0;  // packed (c,c+1)(c+2,c+3) x 2 rows
    const float* x0 = Xs + r0 * 64;
    const float* x1 = x0 + 64;
    #pragma unroll
    for (int k = 0; k < 64; k++) {
        unsigned long long p0 = splat2(x0[k]);
        unsigned long long p1 = splat2(x1[k]);
        ulonglong2 w = *(const ulonglong2*)(Ws + k * 64 + c4);
        ffma2(a00, p0, w.x);
        ffma2(a01, p0, w.y);
        ffma2(a10, p1, w.x);
        ffma2(a11, p1, w.y);
    }
    float di0 = g_dinv[rowbase + r0];
    float di1 = g_dinv[rowbase + r0 + 1];
    float o0, o1, o2, o3;
    unpack2(a00, o0, o1); unpack2(a01, o2, o3);
    float4 q0; q0.x = di0 * o0; q0.y = di0 * o1; q0.z = di0 * o2; q0.w = di0 * o3;
    *(float4*)(out + (rowbase + r0) * 64 + c4) = q0;
    unpack2(a10, o0, o1); unpack2(a11, o2, o3);
    float4 q1; q1.x = di1 * o0; q1.y = di1 * o1; q1.z = di1 * o2; q1.w = di1 * o3;
    *(float4*)(out + (rowbase + r0 + 1) * 64 + c4) = q1;
}

// ---------------- Aggregation + epilogue -----------------------------------
// One warp per dst row. h is pre-scaled by dinv[src], so the loop is a pure
// gather-add. out = dinv[dst]*(sum + h'[dst]) + b; LeakyReLU.
__global__ void k_agg(const float* __restrict__ h, const float* __restrict__ bias,
                      float* __restrict__ out) {
    int wid  = (blockIdx.x * blockDim.x + threadIdx.x) >> 5;
    int lane = threadIdx.x & 31;
    if (wid >= NN) return;
    int start = g_rowptr[wid];
    int cnt   = g_cnt[wid];
    float di  = g_dinv[wid];
    const float2* h2 = (const float2*)h;
    const int* cp = g_col + start;

    float a0 = 0.f, a1 = 0.f;
    int j = 0;
    for (; j + 8 <= cnt; j += 8) {
        int s0 = cp[j + 0], s1 = cp[j + 1], s2 = cp[j + 2], s3 = cp[j + 3];
        int s4 = cp[j + 4], s5 = cp[j + 5], s6 = cp[j + 6], s7 = cp[j + 7];
        float2 v0 = h2[s0 * 32 + lane];
        float2 v1 = h2[s1 * 32 + lane];
        float2 v2 = h2[s2 * 32 + lane];
        float2 v3 = h2[s3 * 32 + lane];
        float2 v4 = h2[s4 * 32 + lane];
        float2 v5 = h2[s5 * 32 + lane];
        float2 v6 = h2[s6 * 32 + lane];
        float2 v7 = h2[s7 * 32 + lane];
        a0 += v0.x; a1 += v0.y;
        a0 += v1.x; a1 += v1.y;
        a0 += v2.x; a1 += v2.y;
        a0 += v3.x; a1 += v3.y;
        a0 += v4.x; a1 += v4.y;
        a0 += v5.x; a1 += v5.y;
        a0 += v6.x; a1 += v6.y;
        a0 += v7.x; a1 += v7.y;
    }
    for (; j < cnt; j++) {
        int s = cp[j];
        float2 v = h2[s * 32 + lane];
        a0 += v.x; a1 += v.y;
    }

    float2 hs = h2[wid * 32 + lane];          // h'[dst] = dinv*h
    float2 bb = ((const float2*)bias)[lane];
    float o0 = di * (a0 + hs.x) + bb.x;
    float o1 = di * (a1 + hs.y) + bb.y;
    o0 = (o0 >= 0.f) ? o0 : NEG * o0;
    o1 = (o1 >= 0.f) ? o1 : NEG * o1;
    float2 oo; oo.x = o0; oo.y = o1;
    ((float2*)out)[wid * 32 + lane] = oo;
}

// ---------------- launch ----------------------------------------------------
extern "C" void kernel_launch(void* const* d_in, const int* in_sizes, int n_in,
                              void* d_out, int out_size) {
    (void)in_sizes; (void)n_in; (void)out_size;
    const float* x  = (const float*)d_in[0];
    const int*   ei = (const int*)d_in[1];
    const int* src = ei;
    const int* dst = ei + EE;
    const float* Wt[4] = { (const float*)d_in[2], (const float*)d_in[4],
                           (const float*)d_in[6], (const float*)d_in[8] };
    const float* bt[4] = { (const float*)d_in[3], (const float*)d_in[5],
                           (const float*)d_in[7], (const float*)d_in[9] };

    float *p_h, *p_a, *p_b;
    cudaGetSymbolAddress((void**)&p_h, g_h);
    cudaGetSymbolAddress((void**)&p_a, g_bufA);
    cudaGetSymbolAddress((void**)&p_b, g_bufB);

    const int NB_SCAN = (NN + 1023) / 1024;   // 98
    const int NB_N256 = (NN + 255) / 256;     // 391
    const int NB_E256 = (EE + 255) / 256;     // 6250

    // CSR build (edge-structure only; shared by all 4 layers)
    k_zero_cnt<<<NB_N256, 256>>>();
    k_hist<<<NB_E256, 256>>>(dst);
    k_scanA<<<NB_SCAN, 1024>>>();
    k_scanB<<<1, 32>>>(NB_SCAN);
    k_scanC<<<NB_N256, 256>>>();
    k_scatter<<<NB_E256, 256>>>(src, dst);

    const int GEMM_BLOCKS = NN / 32;   // 3125 (exact)
    const int AGG_BLOCKS  = NN / 8;    // 12500 (8 warps/block, warp-per-row)

    // layer 1: x -> bufA
    k_gemm<<<GEMM_BLOCKS, 256>>>(x, Wt[0], p_h);
    k_agg<<<AGG_BLOCKS, 256>>>(p_h, bt[0], p_a);
    // layer 2: bufA -> bufB
    k_gemm<<<GEMM_BLOCKS, 256>>>(p_a, Wt[1], p_h);
    k_agg<<<AGG_BLOCKS, 256>>>(p_h, bt[1], p_b);
    // layer 3: bufB -> bufA
    k_gemm<<<GEMM_BLOCKS, 256>>>(p_b, Wt[2], p_h);
    k_agg<<<AGG_BLOCKS, 256>>>(p_h, bt[2], p_a);
    // layer 4: bufA -> d_out
    k_gemm<<<GEMM_BLOCKS, 256>>>(p_a, Wt[3], p_h);
    k_agg<<<AGG_BLOCKS, 256>>>(p_h, bt[3], (float*)d_out);
}

// round 3
// speedup vs baseline: 1.4414x; 1.0060x over previous
#include <cuda_runtime.h>
#include <cuda_fp16.h>
#include <math.h>

#define NN 100000
#define EE 1600000
#define DD 64
#define NEG 0.01f

// ---------------- scratch (device globals) ---------------------------------
__device__ __half2 g_h[NN * 32];   // h' = dinv[row]*(in@W), fp16x2 gather buffer
__device__ float g_bufA[NN * DD];  // ping
__device__ float g_bufB[NN * DD];  // pong
__device__ int   g_cnt[NN];        // in-degree histogram (excl. self loop)
__device__ int   g_rowptr[NN];     // CSR row starts
__device__ int   g_pos[NN];        // running scatter cursor
__device__ int   g_col[EE];        // CSR column (src) indices
__device__ float g_dinv[NN];       // deg^-1/2
__device__ int   g_bsum[128];      // scan block sums (98 used)

// ---------------- f32x2 packed-FMA helpers ---------------------------------
__device__ __forceinline__ unsigned long long splat2(float x) {
    unsigned long long r;
    asm("mov.b64 %0, {%1, %1};" : "=l"(r) : "f"(x));
    return r;
}
__device__ __forceinline__ void ffma2(unsigned long long& d,
                                      unsigned long long a,
                                      unsigned long long b) {
    asm("fma.rn.f32x2 %0, %1, %2, %0;" : "+l"(d) : "l"(a), "l"(b));
}
__device__ __forceinline__ void unpack2(unsigned long long v, float& lo, float& hi) {
    asm("mov.b64 {%0, %1}, %2;" : "=f"(lo), "=f"(hi) : "l"(v));
}

// ---------------- CSR build ------------------------------------------------
__global__ void k_zero_cnt() {
    int i = blockIdx.x * blockDim.x + threadIdx.x;
    if (i < NN) g_cnt[i] = 0;
}

// 4 edges / thread, vectorized
__global__ void k_hist(const int* __restrict__ dst) {
    int t = blockIdx.x * blockDim.x + threadIdx.x;
    if (t * 4 < EE) {
        int4 d = ((const int4*)dst)[t];
        atomicAdd(&g_cnt[d.x], 1);
        atomicAdd(&g_cnt[d.y], 1);
        atomicAdd(&g_cnt[d.z], 1);
        atomicAdd(&g_cnt[d.w], 1);
    }
}

// block-wide inclusive scan (1024 elems/block), writes exclusive partials
__global__ void k_scanA() {
    __shared__ int s[1024];
    int tid = threadIdx.x;
    int i = blockIdx.x * 1024 + tid;
    int v = (i < NN) ? g_cnt[i] : 0;
    if (i < NN) g_dinv[i] = rsqrtf((float)(v + 1));
    s[tid] = v;
    __syncthreads();
    #pragma unroll
    for (int off = 1; off < 1024; off <<= 1) {
        int t = (tid >= off) ? s[tid - off] : 0;
        __syncthreads();
        s[tid] += t;
        __syncthreads();
    }
    if (i < NN) g_rowptr[i] = s[tid] - v;   // exclusive within block
    if (tid == 1023) g_bsum[blockIdx.x] = s[1023];
}

// parallel scan of the (<=128) block sums: 1 warp, 4 elems/thread
__global__ void k_scanB(int nb) {
    int lane = threadIdx.x;
    int base = lane * 4;
    int v0 = (base + 0 < nb) ? g_bsum[base + 0] : 0;
    int v1 = (base + 1 < nb) ? g_bsum[base + 1] : 0;
    int v2 = (base + 2 < nb) ? g_bsum[base + 2] : 0;
    int v3 = (base + 3 < nb) ? g_bsum[base + 3] : 0;
    int s1 = v0 + v1, s2 = s1 + v2, s3 = s2 + v3;
    int tot = s3;
    int run = tot;
    #pragma unroll
    for (int off = 1; off < 32; off <<= 1) {
        int t = __shfl_up_sync(0xffffffffu, run, off);
        if (lane >= off) run += t;
    }
    int excl = run - tot;
    if (base + 0 < nb) g_bsum[base + 0] = excl;
    if (base + 1 < nb) g_bsum[base + 1] = excl + v0;
    if (base + 2 < nb) g_bsum[base + 2] = excl + s1;
    if (base + 3 < nb) g_bsum[base + 3] = excl + s2;
}

__global__ void k_scanC() {
    int i = blockIdx.x * blockDim.x + threadIdx.x;
    if (i < NN) {
        int rp = g_rowptr[i] + g_bsum[i >> 10];
        g_rowptr[i] = rp;
        g_pos[i] = rp;
    }
}

// 4 edges / thread, vectorized
__global__ void k_scatter(const int* __restrict__ src, const int* __restrict__ dst) {
    int t = blockIdx.x * blockDim.x + threadIdx.x;
    if (t * 4 < EE) {
        int4 d = ((const int4*)dst)[t];
        int4 s = ((const int4*)src)[t];
        int p0 = atomicAdd(&g_pos[d.x], 1);
        int p1 = atomicAdd(&g_pos[d.y], 1);
        int p2 = atomicAdd(&g_pos[d.z], 1);
        int p3 = atomicAdd(&g_pos[d.w], 1);
        g_col[p0] = s.x;
        g_col[p1] = s.y;
        g_col[p2] = s.z;
        g_col[p3] = s.w;
    }
}

// ---------------- GEMM: h'[N,64](fp16) = dinv[row]*(in[N,64] @ W[64,64]) ---
// 256 threads / block, 32 rows / block; 2 rows x 4 cols per thread, FFMA2.
__global__ void k_gemm(const float* __restrict__ in, const float* __restrict__ W,
                       __half2* __restrict__ out) {
    __shared__ float Ws[64 * 64];
    __shared__ float Xs[32 * 64];
    int tid = threadIdx.x;
    #pragma unroll
    for (int j = tid; j < 4096; j += 256) Ws[j] = W[j];
    int rowbase = blockIdx.x * 32;
    ((float4*)Xs)[tid]       = ((const float4*)(in + rowbase * 64))[tid];
    ((float4*)Xs)[tid + 256] = ((const float4*)(in + rowbase * 64))[tid + 256];
    __syncthreads();

    int rp = tid >> 4;
    int r0 = rp * 2;
    int c4 = (tid & 15) * 4;
    unsigned long long a00 = 0, a01 = 0, a10 = 0, a11 = 0;
    const float* x0 = Xs + r0 * 64;
    const float* x1 = x0 + 64;
    #pragma unroll
    for (int k = 0; k < 64; k++) {
        unsigned long long p0 = splat2(x0[k]);
        unsigned long long p1 = splat2(x1[k]);
        ulonglong2 w = *(const ulonglong2*)(Ws + k * 64 + c4);
        ffma2(a00, p0, w.x);
        ffma2(a01, p0, w.y);
        ffma2(a10, p1, w.x);
        ffma2(a11, p1, w.y);
    }
    float di0 = g_dinv[rowbase + r0];
    float di1 = g_dinv[rowbase + r0 + 1];
    float o0, o1, o2, o3;
    unpack2(a00, o0, o1); unpack2(a01, o2, o3);
    __half2 q0 = __floats2half2_rn(di0 * o0, di0 * o1);
    __half2 q1 = __floats2half2_rn(di0 * o2, di0 * o3);
    *(uint2*)(out + (rowbase + r0) * 32 + c4 / 2) =
        make_uint2(*(unsigned*)&q0, *(unsigned*)&q1);
    unpack2(a10, o0, o1); unpack2(a11, o2, o3);
    __half2 q2 = __floats2half2_rn(di1 * o0, di1 * o1);
    __half2 q3 = __floats2half2_rn(di1 * o2, di1 * o3);
    *(uint2*)(out + (rowbase + r0 + 1) * 32 + c4 / 2) =
        make_uint2(*(unsigned*)&q2, *(unsigned*)&q3);
}

// ---------------- Aggregation + epilogue -----------------------------------
// One warp per dst row; fp16 gather (half2 per lane), fp32 accumulate.
__global__ void k_agg(const __half2* __restrict__ h, const float* __restrict__ bias,
                      float* __restrict__ out) {
    int wid  = (blockIdx.x * blockDim.x + threadIdx.x) >> 5;
    int lane = threadIdx.x & 31;
    if (wid >= NN) return;
    int start = g_rowptr[wid];
    int cnt   = g_cnt[wid];
    float di  = g_dinv[wid];
    const int* cp = g_col + start;

    float a0 = 0.f, a1 = 0.f;
    int j = 0;
    for (; j + 8 <= cnt; j += 8) {
        int s0 = cp[j + 0], s1 = cp[j + 1], s2 = cp[j + 2], s3 = cp[j + 3];
        int s4 = cp[j + 4], s5 = cp[j + 5], s6 = cp[j + 6], s7 = cp[j + 7];
        __half2 v0 = h[s0 * 32 + lane];
        __half2 v1 = h[s1 * 32 + lane];
        __half2 v2 = h[s2 * 32 + lane];
        __half2 v3 = h[s3 * 32 + lane];
        __half2 v4 = h[s4 * 32 + lane];
        __half2 v5 = h[s5 * 32 + lane];
        __half2 v6 = h[s6 * 32 + lane];
        __half2 v7 = h[s7 * 32 + lane];
        float2 f0 = __half22float2(v0), f1 = __half22float2(v1);
        float2 f2 = __half22float2(v2), f3 = __half22float2(v3);
        float2 f4 = __half22float2(v4), f5 = __half22float2(v5);
        float2 f6 = __half22float2(v6), f7 = __half22float2(v7);
        a0 += f0.x + f1.x + f2.x + f3.x + f4.x + f5.x + f6.x + f7.x;
        a1 += f0.y + f1.y + f2.y + f3.y + f4.y + f5.y + f6.y + f7.y;
    }
    for (; j < cnt; j++) {
        int s = cp[j];
        float2 f = __half22float2(h[s * 32 + lane]);
        a0 += f.x; a1 += f.y;
    }

    float2 hs = __half22float2(h[wid * 32 + lane]);  // h'[dst] = dinv*h
    float2 bb = ((const float2*)bias)[lane];
    float o0 = di * (a0 + hs.x) + bb.x;
    float o1 = di * (a1 + hs.y) + bb.y;
    o0 = (o0 >= 0.f) ? o0 : NEG * o0;
    o1 = (o1 >= 0.f) ? o1 : NEG * o1;
    float2 oo; oo.x = o0; oo.y = o1;
    ((float2*)out)[wid * 32 + lane] = oo;
}

// ---------------- launch ----------------------------------------------------
extern "C" void kernel_launch(void* const* d_in, const int* in_sizes, int n_in,
                              void* d_out, int out_size) {
    (void)in_sizes; (void)n_in; (void)out_size;
    const float* x  = (const float*)d_in[0];
    const int*   ei = (const int*)d_in[1];
    const int* src = ei;
    const int* dst = ei + EE;
    const float* Wt[4] = { (const float*)d_in[2], (const float*)d_in[4],
                           (const float*)d_in[6], (const float*)d_in[8] };
    const float* bt[4] = { (const float*)d_in[3], (const float*)d_in[5],
                           (const float*)d_in[7], (const float*)d_in[9] };

    __half2* p_h;
    float *p_a, *p_b;
    cudaGetSymbolAddress((void**)&p_h, g_h);
    cudaGetSymbolAddress((void**)&p_a, g_bufA);
    cudaGetSymbolAddress((void**)&p_b, g_bufB);

    const int NB_SCAN = (NN + 1023) / 1024;    // 98
    const int NB_N256 = (NN + 255) / 256;      // 391
    const int NB_E4   = (EE / 4 + 255) / 256;  // 1563

    // CSR build (edge-structure only; shared by all 4 layers)
    k_zero_cnt<<<NB_N256, 256>>>();
    k_hist<<<NB_E4, 256>>>(dst);
    k_scanA<<<NB_SCAN, 1024>>>();
    k_scanB<<<1, 32>>>(NB_SCAN);
    k_scanC<<<NB_N256, 256>>>();
    k_scatter<<<NB_E4, 256>>>(src, dst);

    const int GEMM_BLOCKS = NN / 32;   // 3125 (exact)
    const int AGG_BLOCKS  = NN / 8;    // 12500 (8 warps/block, warp-per-row)

    // layer 1: x -> bufA
    k_gemm<<<GEMM_BLOCKS, 256>>>(x, Wt[0], p_h);
    k_agg<<<AGG_BLOCKS, 256>>>(p_h, bt[0], p_a);
    // layer 2: bufA -> bufB
    k_gemm<<<GEMM_BLOCKS, 256>>>(p_a, Wt[1], p_h);
    k_agg<<<AGG_BLOCKS, 256>>>(p_h, bt[1], p_b);
    // layer 3: bufB -> bufA
    k_gemm<<<GEMM_BLOCKS, 256>>>(p_b, Wt[2], p_h);
    k_agg<<<AGG_BLOCKS, 256>>>(p_h, bt[2], p_a);
    // layer 4: bufA -> d_out
    k_gemm<<<GEMM_BLOCKS, 256>>>(p_a, Wt[3], p_h);
    k_agg<<<AGG_BLOCKS, 256>>>(p_h, bt[3], (float*)d_out);
}

// round 5
// speedup vs baseline: 1.6242x; 1.1268x over previous
#include <cuda_runtime.h>
#include <cuda_fp16.h>
#include <mma.h>
#include <math.h>
#include <stdint.h>

using namespace nvcuda;

#define NN 100000
#define EE 1600000
#define NEG 0.01f

// ---------------- scratch (device globals) ---------------------------------
__device__ __half2 g_h[NN * 32];     // h' = dinv*(in@W), fp16 gather buffer
__device__ __half2 g_bufA[NN * 32];  // fp16 node features (ping)
__device__ __half2 g_bufB[NN * 32];  // fp16 node features (pong)
__device__ int   g_cnt[NN];
__device__ int   g_rowptr[NN];
__device__ int   g_pos[NN];
__device__ int   g_col[EE];
__device__ float g_dinv[NN];
__device__ int   g_bsum[128];

// ---------------- CSR build ------------------------------------------------
__global__ void k_zero_cnt() {
    int i = blockIdx.x * blockDim.x + threadIdx.x;
    if (i < NN) g_cnt[i] = 0;
}

__global__ void k_hist(const int* __restrict__ dst) {
    int t = blockIdx.x * blockDim.x + threadIdx.x;
    if (t * 4 < EE) {
        int4 d = ((const int4*)dst)[t];
        atomicAdd(&g_cnt[d.x], 1);
        atomicAdd(&g_cnt[d.y], 1);
        atomicAdd(&g_cnt[d.z], 1);
        atomicAdd(&g_cnt[d.w], 1);
    }
}

__global__ void k_scanA() {
    __shared__ int s[1024];
    int tid = threadIdx.x;
    int i = blockIdx.x * 1024 + tid;
    int v = (i < NN) ? g_cnt[i] : 0;
    if (i < NN) g_dinv[i] = rsqrtf((float)(v + 1));
    s[tid] = v;
    __syncthreads();
    #pragma unroll
    for (int off = 1; off < 1024; off <<= 1) {
        int t = (tid >= off) ? s[tid - off] : 0;
        __syncthreads();
        s[tid] += t;
        __syncthreads();
    }
    if (i < NN) g_rowptr[i] = s[tid] - v;
    if (tid == 1023) g_bsum[blockIdx.x] = s[1023];
}

__global__ void k_scanB(int nb) {
    int lane = threadIdx.x;
    int base = lane * 4;
    int v0 = (base + 0 < nb) ? g_bsum[base + 0] : 0;
    int v1 = (base + 1 < nb) ? g_bsum[base + 1] : 0;
    int v2 = (base + 2 < nb) ? g_bsum[base + 2] : 0;
    int v3 = (base + 3 < nb) ? g_bsum[base + 3] : 0;
    int s1 = v0 + v1, s2 = s1 + v2, s3 = s2 + v3;
    int tot = s3;
    int run = tot;
    #pragma unroll
    for (int off = 1; off < 32; off <<= 1) {
        int t = __shfl_up_sync(0xffffffffu, run, off);
        if (lane >= off) run += t;
    }
    int excl = run - tot;
    if (base + 0 < nb) g_bsum[base + 0] = excl;
    if (base + 1 < nb) g_bsum[base + 1] = excl + v0;
    if (base + 2 < nb) g_bsum[base + 2] = excl + s1;
    if (base + 3 < nb) g_bsum[base + 3] = excl + s2;
}

__global__ void k_scanC() {
    int i = blockIdx.x * blockDim.x + threadIdx.x;
    if (i < NN) {
        int rp = g_rowptr[i] + g_bsum[i >> 10];
        g_rowptr[i] = rp;
        g_pos[i] = rp;
    }
}

__global__ void k_scatter(const int* __restrict__ src, const int* __restrict__ dst) {
    int t = blockIdx.x * blockDim.x + threadIdx.x;
    if (t * 4 < EE) {
        int4 d = ((const int4*)dst)[t];
        int4 s = ((const int4*)src)[t];
        int p0 = atomicAdd(&g_pos[d.x], 1);
        int p1 = atomicAdd(&g_pos[d.y], 1);
        int p2 = atomicAdd(&g_pos[d.z], 1);
        int p3 = atomicAdd(&g_pos[d.w], 1);
        g_col[p0] = s.x;
        g_col[p1] = s.y;
        g_col[p2] = s.z;
        g_col[p3] = s.w;
    }
}

// ---------------- WMMA GEMM: h'[N,64](fp16) = dinv[row]*(in @ W) -----------
// 256 threads (8 warps), 128 rows/block. Each warp: 16-row strip, 4 n-tiles.
// fp16 inputs, fp32 accumulate (HMMA).
template<bool F32IN>
__global__ void __launch_bounds__(256) k_gemm_wmma(
    const void* __restrict__ inv, const float* __restrict__ W,
    __half2* __restrict__ out) {
    __shared__ __align__(16) char sraw[24576];
    half* As = (half*)sraw;             // 128 x 64 (ldm 64)
    half* Bs = (half*)(sraw + 16384);   // 64 x 64  (ldm 64)
    int tid  = threadIdx.x;
    int warp = tid >> 5, lane = tid & 31;
    int rowbase = blockIdx.x * 128;

    // load W -> Bs (fp32 -> fp16): 1024 float4, 4 per thread
    #pragma unroll
    for (int k = 0; k < 4; k++) {
        int i = tid + k * 256;
        float4 w = ((const float4*)W)[i];
        __half2 h0 = __floats2half2_rn(w.x, w.y);
        __half2 h1 = __floats2half2_rn(w.z, w.w);
        *(uint2*)(Bs + i * 4) = make_uint2(*(uint32_t*)&h0, *(uint32_t*)&h1);
    }
    // load A tile
    if (F32IN) {
        const float4* in4 = (const float4*)inv;  // 16 float4 per row
        #pragma unroll
        for (int k = 0; k < 8; k++) {
            int i = tid + k * 256;               // 2048 float4
            int row = i >> 4, q = i & 15;
            int gr = rowbase + row;
            float4 v = (gr < NN) ? in4[(size_t)gr * 16 + q] : make_float4(0, 0, 0, 0);
            __half2 h0 = __floats2half2_rn(v.x, v.y);
            __half2 h1 = __floats2half2_rn(v.z, v.w);
            *(uint2*)(As + row * 64 + q * 4) =
                make_uint2(*(uint32_t*)&h0, *(uint32_t*)&h1);
        }
    } else {
        const uint4* in4 = (const uint4*)inv;    // fp16 rows: 8 uint4 per row
        #pragma unroll
        for (int k = 0; k < 4; k++) {
            int i = tid + k * 256;               // 1024 uint4
            int row = i >> 3, q = i & 7;
            int gr = rowbase + row;
            uint4 v = (gr < NN) ? in4[(size_t)gr * 8 + q] : make_uint4(0, 0, 0, 0);
            *(uint4*)(As + row * 64 + q * 8) = v;
        }
    }
    __syncthreads();

    wmma::fragment<wmma::accumulator, 16, 16, 16, float> c[4];
    #pragma unroll
    for (int nt = 0; nt < 4; nt++) wmma::fill_fragment(c[nt], 0.0f);

    const half* arow = As + warp * 16 * 64;
    #pragma unroll
    for (int k0 = 0; k0 < 64; k0 += 16) {
        wmma::fragment<wmma::matrix_a, 16, 16, 16, half, wmma::row_major> a;
        wmma::load_matrix_sync(a, arow + k0, 64);
        #pragma unroll
        for (int nt = 0; nt < 4; nt++) {
            wmma::fragment<wmma::matrix_b, 16, 16, 16, half, wmma::row_major> b;
            wmma::load_matrix_sync(b, Bs + k0 * 64 + nt * 16, 64);
            wmma::mma_sync(c[nt], a, b, c[nt]);
        }
    }
    __syncthreads();   // done reading As/Bs; reuse sraw as staging

    // epilogue: per n-tile, stage 16x16 fp32 in warp-private smem, scale, emit
    float* Cst = (float*)sraw + warp * 256;   // 1KB per warp
    int r = lane >> 1;                        // 0..15
    int chalf = (lane & 1) * 8;               // 0 or 8
    int grow = rowbase + warp * 16 + r;
    float di = (grow < NN) ? g_dinv[grow] : 0.f;
    #pragma unroll
    for (int nt = 0; nt < 4; nt++) {
        wmma::store_matrix_sync(Cst, c[nt], 16, wmma::mem_row_major);
        __syncwarp();
        if (grow < NN) {
            float4 v0 = *(const float4*)(Cst + r * 16 + chalf);
            float4 v1 = *(const float4*)(Cst + r * 16 + chalf + 4);
            __half2 h0 = __floats2half2_rn(di * v0.x, di * v0.y);
            __half2 h1 = __floats2half2_rn(di * v0.z, di * v0.w);
            __half2 h2 = __floats2half2_rn(di * v1.x, di * v1.y);
            __half2 h3 = __floats2half2_rn(di * v1.z, di * v1.w);
            *(uint4*)(out + (size_t)grow * 32 + nt * 8 + (lane & 1) * 4) =
                make_uint4(*(uint32_t*)&h0, *(uint32_t*)&h1,
                           *(uint32_t*)&h2, *(uint32_t*)&h3);
        }
        __syncwarp();
    }
}

// ---------------- Aggregation + epilogue -----------------------------------
// One warp per dst row; fp16 gather, fp32 accumulate.
template<bool HALF_OUT>
__global__ void k_agg(const __half2* __restrict__ h, const float* __restrict__ bias,
                      void* __restrict__ outv) {
    int wid  = (blockIdx.x * blockDim.x + threadIdx.x) >> 5;
    int lane = threadIdx.x & 31;
    if (wid >= NN) return;
    int start = g_rowptr[wid];
    int cnt   = g_cnt[wid];
    float di  = g_dinv[wid];
    const int* cp = g_col + start;

    float a0 = 0.f, a1 = 0.f;
    int j = 0;
    for (; j + 8 <= cnt; j += 8) {
        int s0 = cp[j + 0], s1 = cp[j + 1], s2 = cp[j + 2], s3 = cp[j + 3];
        int s4 = cp[j + 4], s5 = cp[j + 5], s6 = cp[j + 6], s7 = cp[j + 7];
        __half2 v0 = h[s0 * 32 + lane];
        __half2 v1 = h[s1 * 32 + lane];
        __half2 v2 = h[s2 * 32 + lane];
        __half2 v3 = h[s3 * 32 + lane];
        __half2 v4 = h[s4 * 32 + lane];
        __half2 v5 = h[s5 * 32 + lane];
        __half2 v6 = h[s6 * 32 + lane];
        __half2 v7 = h[s7 * 32 + lane];
        float2 f0 = __half22float2(v0), f1 = __half22float2(v1);
        float2 f2 = __half22float2(v2), f3 = __half22float2(v3);
        float2 f4 = __half22float2(v4), f5 = __half22float2(v5);
        float2 f6 = __half22float2(v6), f7 = __half22float2(v7);
        a0 += f0.x + f1.x + f2.x + f3.x + f4.x + f5.x + f6.x + f7.x;
        a1 += f0.y + f1.y + f2.y + f3.y + f4.y + f5.y + f6.y + f7.y;
    }
    for (; j < cnt; j++) {
        int s = cp[j];
        float2 f = __half22float2(h[s * 32 + lane]);
        a0 += f.x; a1 += f.y;
    }

    float2 hs = __half22float2(h[wid * 32 + lane]);
    float2 bb = ((const float2*)bias)[lane];
    float o0 = di * (a0 + hs.x) + bb.x;
    float o1 = di * (a1 + hs.y) + bb.y;
    o0 = (o0 >= 0.f) ? o0 : NEG * o0;
    o1 = (o1 >= 0.f) ? o1 : NEG * o1;
    if (HALF_OUT) {
        ((__half2*)outv)[(size_t)wid * 32 + lane] = __floats2half2_rn(o0, o1);
    } else {
        float2 oo; oo.x = o0; oo.y = o1;
        ((float2*)outv)[(size_t)wid * 32 + lane] = oo;
    }
}

// ---------------- launch ----------------------------------------------------
extern "C" void kernel_launch(void* const* d_in, const int* in_sizes, int n_in,
                              void* d_out, int out_size) {
    (void)in_sizes; (void)n_in; (void)out_size;
    const float* x  = (const float*)d_in[0];
    const int*   ei = (const int*)d_in[1];
    const int* src = ei;
    const int* dst = ei + EE;
    const float* Wt[4] = { (const float*)d_in[2], (const float*)d_in[4],
                           (const float*)d_in[6], (const float*)d_in[8] };
    const float* bt[4] = { (const float*)d_in[3], (const float*)d_in[5],
                           (const float*)d_in[7], (const float*)d_in[9] };

    __half2 *p_h, *p_a, *p_b;
    cudaGetSymbolAddress((void**)&p_h, g_h);
    cudaGetSymbolAddress((void**)&p_a, g_bufA);
    cudaGetSymbolAddress((void**)&p_b, g_bufB);

    const int NB_SCAN = (NN + 1023) / 1024;    // 98
    const int NB_N256 = (NN + 255) / 256;      // 391
    const int NB_E4   = (EE / 4 + 255) / 256;  // 1563

    // CSR build (edge-structure only; shared by all 4 layers)
    k_zero_cnt<<<NB_N256, 256>>>();
    k_hist<<<NB_E4, 256>>>(dst);
    k_scanA<<<NB_SCAN, 1024>>>();
    k_scanB<<<1, 32>>>(NB_SCAN);
    k_scanC<<<NB_N256, 256>>>();
    k_scatter<<<NB_E4, 256>>>(src, dst);

    const int GEMM_BLOCKS = (NN + 127) / 128;  // 782
    const int AGG_BLOCKS  = NN / 8;            // 12500

    // layer 1
    k_gemm_wmma<true ><<<GEMM_BLOCKS, 256>>>(x,   Wt[0], p_h);
    k_agg<true ><<<AGG_BLOCKS, 256>>>(p_h, bt[0], p_a);
    // layer 2
    k_gemm_wmma<false><<<GEMM_BLOCKS, 256>>>(p_a, Wt[1], p_h);
    k_agg<true ><<<AGG_BLOCKS, 256>>>(p_h, bt[1], p_b);
    // layer 3
    k_gemm_wmma<false><<<GEMM_BLOCKS, 256>>>(p_b, Wt[2], p_h);
    k_agg<true ><<<AGG_BLOCKS, 256>>>(p_h, bt[2], p_a);
    // layer 4
    k_gemm_wmma<false><<<GEMM_BLOCKS, 256>>>(p_a, Wt[3], p_h);
    k_agg<false><<<AGG_BLOCKS, 256>>>(p_h, bt[3], d_out);
}